// round 11
// baseline (speedup 1.0000x reference)
#include <cuda_runtime.h>
#include <cstdint>

#define B_SZ 128
#define N_SZ 2048
#define H_SZ 64
#define S_SZ 64
#define IN_STRIDE 68

// ---------------- scratch (device globals: allowed) ----------------
__device__ float g_hA[(size_t)B_SZ * N_SZ * H_SZ];   // 64 MB
__device__ float g_hB[(size_t)B_SZ * N_SZ * H_SZ];   // 64 MB
__device__ float g_agg[3 * B_SZ * S_SZ * H_SZ];      // 6 MB  (agg0|agg1|agg2)
__device__ float g_aggW[B_SZ * S_SZ * H_SZ];         // 2 MB
__device__ float g_wfrag[2 * 8192];                  // frag tables: uint4-interleaved hi|lo

// ---------------- tf32 helpers ----------------
__device__ __forceinline__ uint32_t f2tf32(float v) {
    uint32_t r; asm("cvt.rna.tf32.f32 %0, %1;" : "=r"(r) : "f"(v)); return r;
}
__device__ __forceinline__ void mma_tf32(float* c,
                                         uint32_t a0, uint32_t a1, uint32_t a2, uint32_t a3,
                                         uint32_t b0, uint32_t b1) {
    asm volatile("mma.sync.aligned.m16n8k8.row.col.f32.tf32.tf32.f32 "
                 "{%0,%1,%2,%3},{%4,%5,%6,%7},{%8,%9},{%0,%1,%2,%3};"
                 : "+f"(c[0]), "+f"(c[1]), "+f"(c[2]), "+f"(c[3])
                 : "r"(a0), "r"(a1), "r"(a2), "r"(a3), "r"(b0), "r"(b1));
}

// ---------------- prep: zero agg (blocks 0..1535) + W frag tables (1536,1537) ----------
// frag float idx f = ((kt*8+nt)*32+lane)*4 + q ; q∈{0,1}: hi(j=q), q∈{2,3}: lo(j=q-2)
// k = kt*8 + (lane&3) + j*4 ; n = nt*8 + (lane>>2)
__global__ __launch_bounds__(256)
void prep_kernel(float* __restrict__ agg,
                 const float* __restrict__ W1, const float* __restrict__ W2,
                 float* __restrict__ wf) {
    const int bid = blockIdx.x, tid = threadIdx.x;
    if (bid < 1536) {
        ((float4*)agg)[bid * 256 + tid] = make_float4(0.f, 0.f, 0.f, 0.f);
    } else {
        const int l = bid - 1536;
        const float* W = l ? W2 : W1;       // top 64 rows of each 128x64 weight
        float* dst = wf + l * 8192;
        for (int f = tid; f < 8192; f += 256) {
            int q = f & 3, lane = (f >> 2) & 31, nt = (f >> 7) & 7, kt = f >> 10;
            int j = q & 1;
            int k = kt * 8 + (lane & 3) + j * 4;
            int n = nt * 8 + (lane >> 2);
            float v = W[k * 64 + n];
            uint32_t h = f2tf32(v);
            if (q < 2) dst[f] = __uint_as_float(h);
            else       dst[f] = __uint_as_float(f2tf32(v - __uint_as_float(h)));
        }
    }
}

// ---------------- layer 0: x[B,N,8] @ W0[8,64] -> LN -> relu -> hA, agg0(global REDG) ----
__global__ __launch_bounds__(256)
void layer0_kernel(const float* __restrict__ x,
                   const int* __restrict__ cluster,
                   const float* __restrict__ W0,
                   const float* __restrict__ b0,
                   const float* __restrict__ g,
                   const float* __restrict__ beta,
                   float* __restrict__ hout,
                   float* __restrict__ agg) {
    __shared__ float sX[128 * 8];
    __shared__ float sW0[8 * 64];
    __shared__ int sClu[128];

    const int b = blockIdx.y;
    const int row0 = blockIdx.x * 128;
    const int tid = threadIdx.x;

    ((float4*)sX)[tid] = ((const float4*)(x + ((size_t)b * N_SZ + row0) * 8))[tid];
    if (tid < 128) ((float4*)sW0)[tid] = ((const float4*)W0)[tid];
    if (tid < 128) sClu[tid] = cluster[(size_t)b * N_SZ + row0 + tid];
    __syncthreads();

    const int warp = tid >> 5, lane = tid & 31;
    const float bc0 = b0[lane], bc1 = b0[lane + 32];
    const float gc0 = g[lane], gc1 = g[lane + 32];
    const float bt0 = beta[lane], bt1 = beta[lane + 32];
    int* gaggI = (int*)(agg + (size_t)b * 4096);

    for (int r = warp * 16; r < warp * 16 + 16; r++) {
        float v0 = bc0, v1 = bc1;
#pragma unroll
        for (int k = 0; k < 8; k++) {
            float xv = sX[r * 8 + k];
            v0 = fmaf(xv, sW0[k * 64 + lane], v0);
            v1 = fmaf(xv, sW0[k * 64 + lane + 32], v1);
        }
        float s1 = v0 + v1;
        float s2 = fmaf(v0, v0, v1 * v1);
#pragma unroll
        for (int off = 16; off > 0; off >>= 1) {
            s1 += __shfl_xor_sync(0xffffffffu, s1, off);
            s2 += __shfl_xor_sync(0xffffffffu, s2, off);
        }
        float mu = s1 * 0.015625f;
        float var = fmaf(-mu, mu, s2 * 0.015625f);
        float rs = rsqrtf(var + 1e-5f);
        float o0 = fmaxf(0.f, fmaf((v0 - mu) * rs, gc0, bt0));
        float o1 = fmaxf(0.f, fmaf((v1 - mu) * rs, gc1, bt1));
        size_t base = ((size_t)b * N_SZ + row0 + r) * H_SZ;
        hout[base + lane] = o0;
        hout[base + lane + 32] = o1;
        int s = sClu[r];
        if (o0 > 0.f) atomicMax(&gaggI[s * 64 + lane], __float_as_int(o0));
        if (o1 > 0.f) atomicMax(&gaggI[s * 64 + lane + 32], __float_as_int(o1));
    }
}

// ---------------- aggw: aggW[b,s,:] = agg[b,s,:] @ Wbot[64,64] + bias  (grid 4 x 128) ----
__global__ __launch_bounds__(256)
void aggw_kernel(const float* __restrict__ agg,
                 const float* __restrict__ Wbot,
                 const float* __restrict__ bias,
                 float* __restrict__ aggW) {
    __shared__ float sA[16 * 64];
    __shared__ float sW[64 * 64];
    const int b = blockIdx.y;
    const int sg0 = blockIdx.x * 16;
    const int tid = threadIdx.x;

    for (int i = tid; i < 1024; i += 256) ((float4*)sW)[i] = ((const float4*)Wbot)[i];
    ((float4*)sA)[tid] = ((const float4*)(agg + (size_t)b * 4096 + sg0 * 64))[tid];
    __syncthreads();

    const int s = tid >> 4;               // 0..15 local segment
    const int c0 = (tid & 15) << 2;       // 0,4,...,60
    float4 bv = *(const float4*)(bias + c0);
    float a0 = bv.x, a1 = bv.y, a2 = bv.z, a3 = bv.w;
#pragma unroll 8
    for (int k = 0; k < 64; k++) {
        float a = sA[s * 64 + k];
        float4 w = *(const float4*)&sW[k * 64 + c0];
        a0 = fmaf(a, w.x, a0);
        a1 = fmaf(a, w.y, a1);
        a2 = fmaf(a, w.z, a2);
        a3 = fmaf(a, w.w, a3);
    }
    *(float4*)(aggW + (size_t)b * 4096 + (sg0 + s) * 64 + c0) = make_float4(a0, a1, a2, a3);
}

// ---------------- layers 1/2 (tf32 mma, register LN epilogue, B frags via LDG) -----------
// dyn smem: sIn[128*IN_STRIDE] | sClu[128]
#define SMEM_LAYER ((128 * IN_STRIDE + 128) * 4)

template <bool WRITE_H>
__global__ __launch_bounds__(256, 4)
void layer_kernel(const float* __restrict__ hin,
                  const float* __restrict__ aggW,
                  const int* __restrict__ cluster,
                  const float* __restrict__ wf,
                  const float* __restrict__ g,
                  const float* __restrict__ beta,
                  float* __restrict__ hout,
                  float* __restrict__ agg) {
    extern __shared__ float smem[];
    float* sIn = smem;                         // 128 * IN_STRIDE
    int* sClu = (int*)(smem + 128 * IN_STRIDE);

    const int b = blockIdx.y;
    const int row0 = blockIdx.x * 128;
    const int tid = threadIdx.x;

    {   // input tile: 128x64 floats, row stride IN_STRIDE
        const float4* src = (const float4*)(hin + ((size_t)b * N_SZ + row0) * H_SZ);
#pragma unroll
        for (int i = 0; i < 8; i++) {
            int idx = tid + 256 * i;
            int r = idx >> 4, c4 = idx & 15;
            *(float4*)&sIn[r * IN_STRIDE + c4 * 4] = src[idx];
        }
    }
    if (tid < 128) sClu[tid] = cluster[(size_t)b * N_SZ + row0 + tid];
    __syncthreads();

    const int warp = tid >> 5, lane = tid & 31;
    const int gy = lane >> 2, gx = lane & 3;
    const int rbase = warp * 16;
    const uint4* wfu = (const uint4*)wf;       // (bh.x,bh.y,bl.x,bl.y) per (kt,nt,lane)

    float acc[8][4];
#pragma unroll
    for (int i = 0; i < 8; i++)
#pragma unroll
        for (int j = 0; j < 4; j++) acc[i][j] = 0.f;

#pragma unroll
    for (int kt = 0; kt < 8; kt++) {
        float va0 = sIn[(rbase + gy) * IN_STRIDE + kt * 8 + gx];
        float va1 = sIn[(rbase + gy + 8) * IN_STRIDE + kt * 8 + gx];
        float va2 = sIn[(rbase + gy) * IN_STRIDE + kt * 8 + gx + 4];
        float va3 = sIn[(rbase + gy + 8) * IN_STRIDE + kt * 8 + gx + 4];
        uint32_t ah0 = f2tf32(va0), ah1 = f2tf32(va1), ah2 = f2tf32(va2), ah3 = f2tf32(va3);
        uint32_t al0 = f2tf32(va0 - __uint_as_float(ah0));
        uint32_t al1 = f2tf32(va1 - __uint_as_float(ah1));
        uint32_t al2 = f2tf32(va2 - __uint_as_float(ah2));
        uint32_t al3 = f2tf32(va3 - __uint_as_float(ah3));
#pragma unroll
        for (int nt = 0; nt < 8; nt++) {
            uint4 bf = __ldg(&wfu[(kt * 8 + nt) * 32 + lane]);
            mma_tf32(acc[nt], ah0, ah1, ah2, ah3, bf.x, bf.y);
            mma_tf32(acc[nt], al0, al1, al2, al3, bf.x, bf.y);
            mma_tf32(acc[nt], ah0, ah1, ah2, ah3, bf.z, bf.w);
        }
    }

    // ---- register epilogue: gather aggW, LN via quad-shuffles, relu, store, segmax ----
    const int r0 = rbase + gy, r1 = rbase + gy + 8;
    const int sa = sClu[r0], sb = sClu[r1];
    const float* aggWb = aggW + (size_t)b * 4096;
    const float* gA = aggWb + sa * 64 + gx * 2;
    const float* gB = aggWb + sb * 64 + gx * 2;

    float s1a = 0.f, s2a = 0.f, s1b = 0.f, s2b = 0.f;
#pragma unroll
    for (int nt = 0; nt < 8; nt++) {
        float2 ga = *(const float2*)(gA + nt * 8);
        float2 gb = *(const float2*)(gB + nt * 8);
        acc[nt][0] += ga.x; acc[nt][1] += ga.y;
        acc[nt][2] += gb.x; acc[nt][3] += gb.y;
        s1a += acc[nt][0] + acc[nt][1];
        s2a = fmaf(acc[nt][0], acc[nt][0], fmaf(acc[nt][1], acc[nt][1], s2a));
        s1b += acc[nt][2] + acc[nt][3];
        s2b = fmaf(acc[nt][2], acc[nt][2], fmaf(acc[nt][3], acc[nt][3], s2b));
    }
    s1a += __shfl_xor_sync(0xffffffffu, s1a, 1);
    s1a += __shfl_xor_sync(0xffffffffu, s1a, 2);
    s2a += __shfl_xor_sync(0xffffffffu, s2a, 1);
    s2a += __shfl_xor_sync(0xffffffffu, s2a, 2);
    s1b += __shfl_xor_sync(0xffffffffu, s1b, 1);
    s1b += __shfl_xor_sync(0xffffffffu, s1b, 2);
    s2b += __shfl_xor_sync(0xffffffffu, s2b, 1);
    s2b += __shfl_xor_sync(0xffffffffu, s2b, 2);

    float mua = s1a * 0.015625f;
    float rsa = rsqrtf(fmaf(-mua, mua, s2a * 0.015625f) + 1e-5f);
    float mub = s1b * 0.015625f;
    float rsb = rsqrtf(fmaf(-mub, mub, s2b * 0.015625f) + 1e-5f);

    int* gaggI = (int*)(agg + (size_t)b * 4096);
    float* hA_ = WRITE_H ? (hout + ((size_t)b * N_SZ + row0 + r0) * H_SZ + gx * 2) : nullptr;
    float* hB_ = WRITE_H ? (hout + ((size_t)b * N_SZ + row0 + r1) * H_SZ + gx * 2) : nullptr;

#pragma unroll
    for (int nt = 0; nt < 8; nt++) {
        const int c = nt * 8 + gx * 2;
        float2 gv = *(const float2*)(g + c);
        float2 bv = *(const float2*)(beta + c);
        float oa0 = fmaxf(0.f, fmaf((acc[nt][0] - mua) * rsa, gv.x, bv.x));
        float oa1 = fmaxf(0.f, fmaf((acc[nt][1] - mua) * rsa, gv.y, bv.y));
        float ob0 = fmaxf(0.f, fmaf((acc[nt][2] - mub) * rsb, gv.x, bv.x));
        float ob1 = fmaxf(0.f, fmaf((acc[nt][3] - mub) * rsb, gv.y, bv.y));
        if (WRITE_H) {
            *(float2*)(hA_ + nt * 8) = make_float2(oa0, oa1);
            *(float2*)(hB_ + nt * 8) = make_float2(ob0, ob1);
        }
        if (oa0 > 0.f) atomicMax(&gaggI[sa * 64 + c], __float_as_int(oa0));
        if (oa1 > 0.f) atomicMax(&gaggI[sa * 64 + c + 1], __float_as_int(oa1));
        if (ob0 > 0.f) atomicMax(&gaggI[sb * 64 + c], __float_as_int(ob0));
        if (ob1 > 0.f) atomicMax(&gaggI[sb * 64 + c + 1], __float_as_int(ob1));
    }
}

// ---------------- final: out[b,s,c] = out[b,s,c+64] = agg2[b,s,c]/max(||.||_segs, 1e-12) ----
__global__ __launch_bounds__(256)
void final_kernel(const float* __restrict__ agg2, float* __restrict__ out) {
    __shared__ float sA[64 * 64];
    __shared__ float sInv[64];
    const int b = blockIdx.x, tid = threadIdx.x;
    for (int i = tid; i < 4096; i += 256) sA[i] = agg2[(size_t)b * 4096 + i];
    __syncthreads();
    if (tid < 64) {
        float nsum = 0.f;
#pragma unroll 8
        for (int s = 0; s < 64; s++) {
            float v = sA[s * 64 + tid];
            nsum = fmaf(v, v, nsum);
        }
        float nrm = sqrtf(nsum);
        sInv[tid] = 1.f / fmaxf(nrm, 1e-12f);
    }
    __syncthreads();
    for (int i = tid; i < 8192; i += 256) {
        int s = i >> 7, ch = i & 127, c = ch & 63;
        out[(size_t)b * 8192 + i] = sA[s * 64 + c] * sInv[c];
    }
}

// ---------------- launch ----------------
extern "C" void kernel_launch(void* const* d_in, const int* in_sizes, int n_in,
                              void* d_out, int out_size) {
    const float* x = (const float*)d_in[0];
    const int* cluster = (const int*)d_in[1];
    const float* W0 = (const float*)d_in[2];
    const float* b0 = (const float*)d_in[3];
    const float* g0 = (const float*)d_in[4];
    const float* be0 = (const float*)d_in[5];
    const float* W1 = (const float*)d_in[6];
    const float* b1 = (const float*)d_in[7];
    const float* g1 = (const float*)d_in[8];
    const float* be1 = (const float*)d_in[9];
    const float* W2 = (const float*)d_in[10];
    const float* b2 = (const float*)d_in[11];
    const float* g2 = (const float*)d_in[12];
    const float* be2 = (const float*)d_in[13];
    float* out = (float*)d_out;

    float *hA, *hB, *agg, *aggW, *wfrag;
    cudaGetSymbolAddress((void**)&hA, g_hA);
    cudaGetSymbolAddress((void**)&hB, g_hB);
    cudaGetSymbolAddress((void**)&agg, g_agg);
    cudaGetSymbolAddress((void**)&aggW, g_aggW);
    cudaGetSymbolAddress((void**)&wfrag, g_wfrag);
    float* agg0 = agg;
    float* agg1 = agg + (size_t)B_SZ * 4096;
    float* agg2 = agg + (size_t)2 * B_SZ * 4096;

    cudaFuncSetAttribute(layer_kernel<true>, cudaFuncAttributeMaxDynamicSharedMemorySize, SMEM_LAYER);
    cudaFuncSetAttribute(layer_kernel<false>, cudaFuncAttributeMaxDynamicSharedMemorySize, SMEM_LAYER);

    prep_kernel<<<1538, 256>>>(agg, W1, W2, wfrag);

    dim3 grid(N_SZ / 128, B_SZ);
    dim3 agrid(4, B_SZ);
    layer0_kernel<<<grid, 256>>>(x, cluster, W0, b0, g0, be0, hA, agg0);
    aggw_kernel<<<agrid, 256>>>(agg0, W1 + 64 * 64, b1, aggW);
    layer_kernel<true><<<grid, 256, SMEM_LAYER>>>(hA, aggW, cluster, wfrag, g1, be1, hB, agg1);
    aggw_kernel<<<agrid, 256>>>(agg1, W2 + 64 * 64, b2, aggW);
    layer_kernel<false><<<grid, 256, SMEM_LAYER>>>(hB, aggW, cluster, wfrag + 8192, g2, be2, nullptr, agg2);
    final_kernel<<<B_SZ, 256>>>(agg2, out);
}

// round 12
// speedup vs baseline: 1.1335x; 1.1335x over previous
#include <cuda_runtime.h>
#include <cuda_bf16.h>
#include <cstdint>

#define B_SZ 128
#define N_SZ 2048
#define H_SZ 64
#define S_SZ 64
#define IN_STRIDE 68

// ---------------- scratch (device globals: allowed) ----------------
__device__ float g_hA[(size_t)B_SZ * N_SZ * H_SZ];   // 64 MB
__device__ float g_hB[(size_t)B_SZ * N_SZ * H_SZ];   // 64 MB
__device__ float g_agg[3 * B_SZ * S_SZ * H_SZ];      // 6 MB  (agg0|agg1|agg2)
__device__ float g_aggW[B_SZ * S_SZ * H_SZ];         // 2 MB
__device__ float g_wfrag[2 * 4096];                  // per-layer bf16 frag tables (16 KB each)

// ---------------- bf16 helpers ----------------
__device__ __forceinline__ uint32_t pack_bf16(float x, float y) {
    __nv_bfloat162 t = __floats2bfloat162_rn(x, y);   // x -> low half, y -> high half
    return *(uint32_t*)&t;
}
__device__ __forceinline__ void mma_bf16(float* c,
                                         uint32_t a0, uint32_t a1, uint32_t a2, uint32_t a3,
                                         uint32_t b0, uint32_t b1) {
    asm volatile("mma.sync.aligned.m16n8k16.row.col.f32.bf16.bf16.f32 "
                 "{%0,%1,%2,%3},{%4,%5,%6,%7},{%8,%9},{%0,%1,%2,%3};"
                 : "+f"(c[0]), "+f"(c[1]), "+f"(c[2]), "+f"(c[3])
                 : "r"(a0), "r"(a1), "r"(a2), "r"(a3), "r"(b0), "r"(b1));
}

// ---------------- prep: zero agg (blocks 0..1535) + bf16 B-frag tables (1536,1537) -------
// entry e = (kt*8+nt)*32 + lane ; uint4 = (bhi0, bhi1, blo0, blo1)
// n = nt*8 + (lane>>2); k0 = kt*16 + (lane&3)*2; pairs (k0,k0+1) and (k0+8,k0+9)
__global__ __launch_bounds__(256)
void prep_kernel(float* __restrict__ agg,
                 const float* __restrict__ W1, const float* __restrict__ W2,
                 float* __restrict__ wf) {
    const int bid = blockIdx.x, tid = threadIdx.x;
    if (bid < 1536) {
        ((float4*)agg)[bid * 256 + tid] = make_float4(0.f, 0.f, 0.f, 0.f);
    } else {
        const int l = bid - 1536;
        const float* W = l ? W2 : W1;              // top 64 rows of each 128x64 weight
        uint4* dst = (uint4*)(wf + l * 4096);
        for (int e = tid; e < 1024; e += 256) {
            int lane = e & 31, nt = (e >> 5) & 7, kt = e >> 8;
            int n = nt * 8 + (lane >> 2);
            int k0 = kt * 16 + (lane & 3) * 2;
            float w00 = W[k0 * 64 + n],       w01 = W[(k0 + 1) * 64 + n];
            float w10 = W[(k0 + 8) * 64 + n], w11 = W[(k0 + 9) * 64 + n];
            float h00 = __bfloat162float(__float2bfloat16_rn(w00));
            float h01 = __bfloat162float(__float2bfloat16_rn(w01));
            float h10 = __bfloat162float(__float2bfloat16_rn(w10));
            float h11 = __bfloat162float(__float2bfloat16_rn(w11));
            uint4 v;
            v.x = pack_bf16(h00, h01);
            v.y = pack_bf16(h10, h11);
            v.z = pack_bf16(w00 - h00, w01 - h01);
            v.w = pack_bf16(w10 - h10, w11 - h11);
            dst[e] = v;
        }
    }
}

// ---------------- layer 0: x[B,N,8] @ W0[8,64] -> LN -> relu -> hA, agg0(global REDG) ----
__global__ __launch_bounds__(256)
void layer0_kernel(const float* __restrict__ x,
                   const int* __restrict__ cluster,
                   const float* __restrict__ W0,
                   const float* __restrict__ b0,
                   const float* __restrict__ g,
                   const float* __restrict__ beta,
                   float* __restrict__ hout,
                   float* __restrict__ agg) {
    __shared__ float sX[128 * 8];
    __shared__ float sW0[8 * 64];
    __shared__ int sClu[128];

    const int b = blockIdx.y;
    const int row0 = blockIdx.x * 128;
    const int tid = threadIdx.x;

    ((float4*)sX)[tid] = ((const float4*)(x + ((size_t)b * N_SZ + row0) * 8))[tid];
    if (tid < 128) ((float4*)sW0)[tid] = ((const float4*)W0)[tid];
    if (tid < 128) sClu[tid] = cluster[(size_t)b * N_SZ + row0 + tid];
    __syncthreads();

    const int warp = tid >> 5, lane = tid & 31;
    const float bc0 = b0[lane], bc1 = b0[lane + 32];
    const float gc0 = g[lane], gc1 = g[lane + 32];
    const float bt0 = beta[lane], bt1 = beta[lane + 32];
    int* gaggI = (int*)(agg + (size_t)b * 4096);

    for (int r = warp * 16; r < warp * 16 + 16; r++) {
        float v0 = bc0, v1 = bc1;
#pragma unroll
        for (int k = 0; k < 8; k++) {
            float xv = sX[r * 8 + k];
            v0 = fmaf(xv, sW0[k * 64 + lane], v0);
            v1 = fmaf(xv, sW0[k * 64 + lane + 32], v1);
        }
        float s1 = v0 + v1;
        float s2 = fmaf(v0, v0, v1 * v1);
#pragma unroll
        for (int off = 16; off > 0; off >>= 1) {
            s1 += __shfl_xor_sync(0xffffffffu, s1, off);
            s2 += __shfl_xor_sync(0xffffffffu, s2, off);
        }
        float mu = s1 * 0.015625f;
        float var = fmaf(-mu, mu, s2 * 0.015625f);
        float rs = rsqrtf(var + 1e-5f);
        float o0 = fmaxf(0.f, fmaf((v0 - mu) * rs, gc0, bt0));
        float o1 = fmaxf(0.f, fmaf((v1 - mu) * rs, gc1, bt1));
        size_t base = ((size_t)b * N_SZ + row0 + r) * H_SZ;
        hout[base + lane] = o0;
        hout[base + lane + 32] = o1;
        int s = sClu[r];
        if (o0 > 0.f) atomicMax(&gaggI[s * 64 + lane], __float_as_int(o0));
        if (o1 > 0.f) atomicMax(&gaggI[s * 64 + lane + 32], __float_as_int(o1));
    }
}

// ---------------- aggw: aggW[b,s,:] = agg[b,s,:] @ Wbot[64,64] + bias  (grid 4 x 128) ----
__global__ __launch_bounds__(256)
void aggw_kernel(const float* __restrict__ agg,
                 const float* __restrict__ Wbot,
                 const float* __restrict__ bias,
                 float* __restrict__ aggW) {
    __shared__ float sA[16 * 64];
    __shared__ float sW[64 * 64];
    const int b = blockIdx.y;
    const int sg0 = blockIdx.x * 16;
    const int tid = threadIdx.x;

    for (int i = tid; i < 1024; i += 256) ((float4*)sW)[i] = ((const float4*)Wbot)[i];
    ((float4*)sA)[tid] = ((const float4*)(agg + (size_t)b * 4096 + sg0 * 64))[tid];
    __syncthreads();

    const int s = tid >> 4;               // 0..15 local segment
    const int c0 = (tid & 15) << 2;       // 0,4,...,60
    float4 bv = *(const float4*)(bias + c0);
    float a0 = bv.x, a1 = bv.y, a2 = bv.z, a3 = bv.w;
#pragma unroll 8
    for (int k = 0; k < 64; k++) {
        float a = sA[s * 64 + k];
        float4 w = *(const float4*)&sW[k * 64 + c0];
        a0 = fmaf(a, w.x, a0);
        a1 = fmaf(a, w.y, a1);
        a2 = fmaf(a, w.z, a2);
        a3 = fmaf(a, w.w, a3);
    }
    *(float4*)(aggW + (size_t)b * 4096 + (sg0 + s) * 64 + c0) = make_float4(a0, a1, a2, a3);
}

// ---------------- layers 1/2 (bf16 m16n8k16 3-split, register LN epilogue) ---------------
// dyn smem: sHi[128*36 u32 bf16x2] | sLo[128*36] | sClu[128]
#define A_STRIDE 36                              /* u32 per row: 32 data + 4 pad */
#define SMEM_LAYER ((128 * A_STRIDE * 2 + 128) * 4)

template <bool WRITE_H>
__global__ __launch_bounds__(256, 4)
void layer_kernel(const float* __restrict__ hin,
                  const float* __restrict__ aggW,
                  const int* __restrict__ cluster,
                  const float* __restrict__ wf,    // per-layer frag table (4096 floats)
                  const float* __restrict__ g,
                  const float* __restrict__ beta,
                  float* __restrict__ hout,
                  float* __restrict__ agg) {
    extern __shared__ uint32_t smemu[];
    uint32_t* sHi = smemu;                        // 128 * A_STRIDE
    uint32_t* sLo = smemu + 128 * A_STRIDE;       // 128 * A_STRIDE
    int* sClu = (int*)(smemu + 2 * 128 * A_STRIDE);

    const int b = blockIdx.y;
    const int row0 = blockIdx.x * 128;
    const int tid = threadIdx.x;

    {   // stage input tile as bf16 hi/lo (k-pairs packed in u32)
        const float4* src = (const float4*)(hin + ((size_t)b * N_SZ + row0) * H_SZ);
#pragma unroll
        for (int i = 0; i < 8; i++) {
            int idx = tid + 256 * i;              // 0..2047 float4s
            int r = idx >> 4, c4 = idx & 15;
            float4 v = src[idx];
            float hx = __bfloat162float(__float2bfloat16_rn(v.x));
            float hy = __bfloat162float(__float2bfloat16_rn(v.y));
            float hz = __bfloat162float(__float2bfloat16_rn(v.z));
            float hw = __bfloat162float(__float2bfloat16_rn(v.w));
            uint32_t base = r * A_STRIDE + c4 * 2;
            *(uint2*)&sHi[base] = make_uint2(pack_bf16(hx, hy), pack_bf16(hz, hw));
            *(uint2*)&sLo[base] = make_uint2(pack_bf16(v.x - hx, v.y - hy),
                                             pack_bf16(v.z - hz, v.w - hw));
        }
    }
    if (tid < 128) sClu[tid] = cluster[(size_t)b * N_SZ + row0 + tid];
    __syncthreads();

    const int warp = tid >> 5, lane = tid & 31;
    const int gy = lane >> 2, gx = lane & 3;
    const int rbase = warp * 16;
    const uint4* wfu = (const uint4*)wf;          // (bhi0,bhi1,blo0,blo1) per (kt,nt,lane)

    float acc[8][4];
#pragma unroll
    for (int i = 0; i < 8; i++)
#pragma unroll
        for (int j = 0; j < 4; j++) acc[i][j] = 0.f;

#pragma unroll
    for (int kt = 0; kt < 4; kt++) {
        const uint32_t* rH0 = sHi + (rbase + gy) * A_STRIDE + kt * 8;
        const uint32_t* rH1 = sHi + (rbase + gy + 8) * A_STRIDE + kt * 8;
        const uint32_t* rL0 = sLo + (rbase + gy) * A_STRIDE + kt * 8;
        const uint32_t* rL1 = sLo + (rbase + gy + 8) * A_STRIDE + kt * 8;
        uint32_t ah0 = rH0[gx], ah1 = rH1[gx], ah2 = rH0[gx + 4], ah3 = rH1[gx + 4];
        uint32_t al0 = rL0[gx], al1 = rL1[gx], al2 = rL0[gx + 4], al3 = rL1[gx + 4];
#pragma unroll
        for (int nt = 0; nt < 8; nt++) {
            uint4 bf = __ldg(&wfu[(kt * 8 + nt) * 32 + lane]);
            mma_bf16(acc[nt], ah0, ah1, ah2, ah3, bf.x, bf.y);   // hi*hi
            mma_bf16(acc[nt], al0, al1, al2, al3, bf.x, bf.y);   // lo*hi
            mma_bf16(acc[nt], ah0, ah1, ah2, ah3, bf.z, bf.w);   // hi*lo
        }
    }

    // ---- register epilogue: gather aggW, LN via quad-shuffles, relu, store, segmax ----
    const int r0 = rbase + gy, r1 = rbase + gy + 8;
    const int sa = sClu[r0], sb = sClu[r1];
    const float* aggWb = aggW + (size_t)b * 4096;
    const float* gA = aggWb + sa * 64 + gx * 2;
    const float* gB = aggWb + sb * 64 + gx * 2;

    float s1a = 0.f, s2a = 0.f, s1b = 0.f, s2b = 0.f;
#pragma unroll
    for (int nt = 0; nt < 8; nt++) {
        float2 ga = *(const float2*)(gA + nt * 8);
        float2 gb = *(const float2*)(gB + nt * 8);
        acc[nt][0] += ga.x; acc[nt][1] += ga.y;
        acc[nt][2] += gb.x; acc[nt][3] += gb.y;
        s1a += acc[nt][0] + acc[nt][1];
        s2a = fmaf(acc[nt][0], acc[nt][0], fmaf(acc[nt][1], acc[nt][1], s2a));
        s1b += acc[nt][2] + acc[nt][3];
        s2b = fmaf(acc[nt][2], acc[nt][2], fmaf(acc[nt][3], acc[nt][3], s2b));
    }
    s1a += __shfl_xor_sync(0xffffffffu, s1a, 1);
    s1a += __shfl_xor_sync(0xffffffffu, s1a, 2);
    s2a += __shfl_xor_sync(0xffffffffu, s2a, 1);
    s2a += __shfl_xor_sync(0xffffffffu, s2a, 2);
    s1b += __shfl_xor_sync(0xffffffffu, s1b, 1);
    s1b += __shfl_xor_sync(0xffffffffu, s1b, 2);
    s2b += __shfl_xor_sync(0xffffffffu, s2b, 1);
    s2b += __shfl_xor_sync(0xffffffffu, s2b, 2);

    float mua = s1a * 0.015625f;
    float rsa = rsqrtf(fmaf(-mua, mua, s2a * 0.015625f) + 1e-5f);
    float mub = s1b * 0.015625f;
    float rsb = rsqrtf(fmaf(-mub, mub, s2b * 0.015625f) + 1e-5f);

    int* gaggI = (int*)(agg + (size_t)b * 4096);
    float* hA_ = WRITE_H ? (hout + ((size_t)b * N_SZ + row0 + r0) * H_SZ + gx * 2) : nullptr;
    float* hB_ = WRITE_H ? (hout + ((size_t)b * N_SZ + row0 + r1) * H_SZ + gx * 2) : nullptr;

#pragma unroll
    for (int nt = 0; nt < 8; nt++) {
        const int c = nt * 8 + gx * 2;
        float2 gv = *(const float2*)(g + c);
        float2 bv = *(const float2*)(beta + c);
        float oa0 = fmaxf(0.f, fmaf((acc[nt][0] - mua) * rsa, gv.x, bv.x));
        float oa1 = fmaxf(0.f, fmaf((acc[nt][1] - mua) * rsa, gv.y, bv.y));
        float ob0 = fmaxf(0.f, fmaf((acc[nt][2] - mub) * rsb, gv.x, bv.x));
        float ob1 = fmaxf(0.f, fmaf((acc[nt][3] - mub) * rsb, gv.y, bv.y));
        if (WRITE_H) {
            *(float2*)(hA_ + nt * 8) = make_float2(oa0, oa1);
            *(float2*)(hB_ + nt * 8) = make_float2(ob0, ob1);
        }
        if (oa0 > 0.f) atomicMax(&gaggI[sa * 64 + c], __float_as_int(oa0));
        if (oa1 > 0.f) atomicMax(&gaggI[sa * 64 + c + 1], __float_as_int(oa1));
        if (ob0 > 0.f) atomicMax(&gaggI[sb * 64 + c], __float_as_int(ob0));
        if (ob1 > 0.f) atomicMax(&gaggI[sb * 64 + c + 1], __float_as_int(ob1));
    }
}

// ---------------- final: out[b,s,c] = out[b,s,c+64] = agg2[b,s,c]/max(||.||_segs, 1e-12) ----
__global__ __launch_bounds__(256)
void final_kernel(const float* __restrict__ agg2, float* __restrict__ out) {
    __shared__ float sA[64 * 64];
    __shared__ float sInv[64];
    const int b = blockIdx.x, tid = threadIdx.x;
    for (int i = tid; i < 4096; i += 256) sA[i] = agg2[(size_t)b * 4096 + i];
    __syncthreads();
    if (tid < 64) {
        float nsum = 0.f;
#pragma unroll 8
        for (int s = 0; s < 64; s++) {
            float v = sA[s * 64 + tid];
            nsum = fmaf(v, v, nsum);
        }
        float nrm = sqrtf(nsum);
        sInv[tid] = 1.f / fmaxf(nrm, 1e-12f);
    }
    __syncthreads();
    for (int i = tid; i < 8192; i += 256) {
        int s = i >> 7, ch = i & 127, c = ch & 63;
        out[(size_t)b * 8192 + i] = sA[s * 64 + c] * sInv[c];
    }
}

// ---------------- launch ----------------
extern "C" void kernel_launch(void* const* d_in, const int* in_sizes, int n_in,
                              void* d_out, int out_size) {
    const float* x = (const float*)d_in[0];
    const int* cluster = (const int*)d_in[1];
    const float* W0 = (const float*)d_in[2];
    const float* b0 = (const float*)d_in[3];
    const float* g0 = (const float*)d_in[4];
    const float* be0 = (const float*)d_in[5];
    const float* W1 = (const float*)d_in[6];
    const float* b1 = (const float*)d_in[7];
    const float* g1 = (const float*)d_in[8];
    const float* be1 = (const float*)d_in[9];
    const float* W2 = (const float*)d_in[10];
    const float* b2 = (const float*)d_in[11];
    const float* g2 = (const float*)d_in[12];
    const float* be2 = (const float*)d_in[13];
    float* out = (float*)d_out;

    float *hA, *hB, *agg, *aggW, *wfrag;
    cudaGetSymbolAddress((void**)&hA, g_hA);
    cudaGetSymbolAddress((void**)&hB, g_hB);
    cudaGetSymbolAddress((void**)&agg, g_agg);
    cudaGetSymbolAddress((void**)&aggW, g_aggW);
    cudaGetSymbolAddress((void**)&wfrag, g_wfrag);
    float* agg0 = agg;
    float* agg1 = agg + (size_t)B_SZ * 4096;
    float* agg2 = agg + (size_t)2 * B_SZ * 4096;

    cudaFuncSetAttribute(layer_kernel<true>, cudaFuncAttributeMaxDynamicSharedMemorySize, SMEM_LAYER);
    cudaFuncSetAttribute(layer_kernel<false>, cudaFuncAttributeMaxDynamicSharedMemorySize, SMEM_LAYER);

    prep_kernel<<<1538, 256>>>(agg, W1, W2, wfrag);

    dim3 grid(N_SZ / 128, B_SZ);
    dim3 agrid(4, B_SZ);
    layer0_kernel<<<grid, 256>>>(x, cluster, W0, b0, g0, be0, hA, agg0);
    aggw_kernel<<<agrid, 256>>>(agg0, W1 + 64 * 64, b1, aggW);
    layer_kernel<true><<<grid, 256, SMEM_LAYER>>>(hA, aggW, cluster, wfrag, g1, be1, hB, agg1);
    aggw_kernel<<<agrid, 256>>>(agg1, W2 + 64 * 64, b2, aggW);
    layer_kernel<false><<<grid, 256, SMEM_LAYER>>>(hB, aggW, cluster, wfrag + 4096, g2, be2, nullptr, agg2);
    final_kernel<<<B_SZ, 256>>>(agg2, out);
}

// round 13
// speedup vs baseline: 1.2726x; 1.1227x over previous
#include <cuda_runtime.h>
#include <cuda_bf16.h>
#include <cstdint>

#define B_SZ 128
#define N_SZ 2048
#define H_SZ 64
#define S_SZ 64

// ---------------- scratch (device globals: allowed) ----------------
__device__ float g_hA[(size_t)B_SZ * N_SZ * H_SZ];   // 64 MB
__device__ float g_hB[(size_t)B_SZ * N_SZ * H_SZ];   // 64 MB
__device__ float g_agg[3 * B_SZ * S_SZ * H_SZ];      // 6 MB  (agg0|agg1|agg2)
__device__ float g_aggW[B_SZ * S_SZ * H_SZ];         // 2 MB
__device__ float g_wfrag[2 * 4096];                  // per-layer bf16 frag tables (16 KB each)

// ---------------- bf16 helpers ----------------
__device__ __forceinline__ uint32_t pack_bf16(float x, float y) {
    __nv_bfloat162 t = __floats2bfloat162_rn(x, y);   // x -> low half, y -> high half
    return *(uint32_t*)&t;
}
__device__ __forceinline__ void mma_bf16(float* c,
                                         uint32_t a0, uint32_t a1, uint32_t a2, uint32_t a3,
                                         uint32_t b0, uint32_t b1) {
    asm volatile("mma.sync.aligned.m16n8k16.row.col.f32.bf16.bf16.f32 "
                 "{%0,%1,%2,%3},{%4,%5,%6,%7},{%8,%9},{%0,%1,%2,%3};"
                 : "+f"(c[0]), "+f"(c[1]), "+f"(c[2]), "+f"(c[3])
                 : "r"(a0), "r"(a1), "r"(a2), "r"(a3), "r"(b0), "r"(b1));
}

// ---------------- prep: zero agg (blocks 0..1535) + bf16 B-frag tables (1536,1537) -------
// entry e = (kt*8+nt)*32 + lane ; uint4 = (bhi0, bhi1, blo0, blo1)
// n = nt*8 + (lane>>2); k0 = kt*16 + (lane&3)*2; pairs (k0,k0+1) and (k0+8,k0+9)
__global__ __launch_bounds__(256)
void prep_kernel(float* __restrict__ agg,
                 const float* __restrict__ W1, const float* __restrict__ W2,
                 float* __restrict__ wf) {
    const int bid = blockIdx.x, tid = threadIdx.x;
    if (bid < 1536) {
        ((float4*)agg)[bid * 256 + tid] = make_float4(0.f, 0.f, 0.f, 0.f);
    } else {
        const int l = bid - 1536;
        const float* W = l ? W2 : W1;              // top 64 rows of each 128x64 weight
        uint4* dst = (uint4*)(wf + l * 4096);
        for (int e = tid; e < 1024; e += 256) {
            int lane = e & 31, nt = (e >> 5) & 7, kt = e >> 8;
            int n = nt * 8 + (lane >> 2);
            int k0 = kt * 16 + (lane & 3) * 2;
            float w00 = W[k0 * 64 + n],       w01 = W[(k0 + 1) * 64 + n];
            float w10 = W[(k0 + 8) * 64 + n], w11 = W[(k0 + 9) * 64 + n];
            float h00 = __bfloat162float(__float2bfloat16_rn(w00));
            float h01 = __bfloat162float(__float2bfloat16_rn(w01));
            float h10 = __bfloat162float(__float2bfloat16_rn(w10));
            float h11 = __bfloat162float(__float2bfloat16_rn(w11));
            uint4 v;
            v.x = pack_bf16(h00, h01);
            v.y = pack_bf16(h10, h11);
            v.z = pack_bf16(w00 - h00, w01 - h01);
            v.w = pack_bf16(w10 - h10, w11 - h11);
            dst[e] = v;
        }
    }
}

// ---------------- layer 0: x[B,N,8] @ W0[8,64] -> LN -> relu -> hA, agg0(coalesced REDG) --
__global__ __launch_bounds__(256)
void layer0_kernel(const float* __restrict__ x,
                   const int* __restrict__ cluster,
                   const float* __restrict__ W0,
                   const float* __restrict__ b0,
                   const float* __restrict__ g,
                   const float* __restrict__ beta,
                   float* __restrict__ hout,
                   float* __restrict__ agg) {
    __shared__ float sX[128 * 8];
    __shared__ float sW0[8 * 64];
    __shared__ int sClu[128];

    const int b = blockIdx.y;
    const int row0 = blockIdx.x * 128;
    const int tid = threadIdx.x;

    ((float4*)sX)[tid] = ((const float4*)(x + ((size_t)b * N_SZ + row0) * 8))[tid];
    if (tid < 128) ((float4*)sW0)[tid] = ((const float4*)W0)[tid];
    if (tid < 128) sClu[tid] = cluster[(size_t)b * N_SZ + row0 + tid];
    __syncthreads();

    const int warp = tid >> 5, lane = tid & 31;
    const float bc0 = b0[lane], bc1 = b0[lane + 32];
    const float gc0 = g[lane], gc1 = g[lane + 32];
    const float bt0 = beta[lane], bt1 = beta[lane + 32];
    int* gaggI = (int*)(agg + (size_t)b * 4096);

    for (int r = warp * 16; r < warp * 16 + 16; r++) {
        float v0 = bc0, v1 = bc1;
#pragma unroll
        for (int k = 0; k < 8; k++) {
            float xv = sX[r * 8 + k];
            v0 = fmaf(xv, sW0[k * 64 + lane], v0);
            v1 = fmaf(xv, sW0[k * 64 + lane + 32], v1);
        }
        float s1 = v0 + v1;
        float s2 = fmaf(v0, v0, v1 * v1);
#pragma unroll
        for (int off = 16; off > 0; off >>= 1) {
            s1 += __shfl_xor_sync(0xffffffffu, s1, off);
            s2 += __shfl_xor_sync(0xffffffffu, s2, off);
        }
        float mu = s1 * 0.015625f;
        float var = fmaf(-mu, mu, s2 * 0.015625f);
        float rs = rsqrtf(var + 1e-5f);
        float o0 = fmaxf(0.f, fmaf((v0 - mu) * rs, gc0, bt0));
        float o1 = fmaxf(0.f, fmaf((v1 - mu) * rs, gc1, bt1));
        size_t base = ((size_t)b * N_SZ + row0 + r) * H_SZ;
        hout[base + lane] = o0;
        hout[base + lane + 32] = o1;
        int s = sClu[r];
        if (o0 > 0.f) atomicMax(&gaggI[s * 64 + lane], __float_as_int(o0));
        if (o1 > 0.f) atomicMax(&gaggI[s * 64 + lane + 32], __float_as_int(o1));
    }
}

// ---------------- aggw: aggW[b,s,:] = agg[b,s,:] @ Wbot[64,64] + bias  (grid 4 x 128) ----
__global__ __launch_bounds__(256)
void aggw_kernel(const float* __restrict__ agg,
                 const float* __restrict__ Wbot,
                 const float* __restrict__ bias,
                 float* __restrict__ aggW) {
    __shared__ float sA[16 * 64];
    __shared__ float sW[64 * 64];
    const int b = blockIdx.y;
    const int sg0 = blockIdx.x * 16;
    const int tid = threadIdx.x;

    for (int i = tid; i < 1024; i += 256) ((float4*)sW)[i] = ((const float4*)Wbot)[i];
    ((float4*)sA)[tid] = ((const float4*)(agg + (size_t)b * 4096 + sg0 * 64))[tid];
    __syncthreads();

    const int s = tid >> 4;               // 0..15 local segment
    const int c0 = (tid & 15) << 2;       // 0,4,...,60
    float4 bv = *(const float4*)(bias + c0);
    float a0 = bv.x, a1 = bv.y, a2 = bv.z, a3 = bv.w;
#pragma unroll 8
    for (int k = 0; k < 64; k++) {
        float a = sA[s * 64 + k];
        float4 w = *(const float4*)&sW[k * 64 + c0];
        a0 = fmaf(a, w.x, a0);
        a1 = fmaf(a, w.y, a1);
        a2 = fmaf(a, w.z, a2);
        a3 = fmaf(a, w.w, a3);
    }
    *(float4*)(aggW + (size_t)b * 4096 + (sg0 + s) * 64 + c0) = make_float4(a0, a1, a2, a3);
}

// ---------------- layers 1/2 (bf16 m16n8k16 3-split, coalesced two-phase epilogue) -------
// dyn smem: region[9216 u32] = staging sHi|sLo, reused as sO (128 x 66 f32) | sClu[128]
#define A_STRIDE 36                              /* u32 per row: 32 data + 4 pad */
#define O_STRIDE 66
#define SMEM_LAYER ((9216 + 128) * 4)

template <bool WRITE_H>
__global__ __launch_bounds__(256, 4)
void layer_kernel(const float* __restrict__ hin,
                  const float* __restrict__ aggW,
                  const int* __restrict__ cluster,
                  const float* __restrict__ wf,    // per-layer frag table (4096 floats)
                  const float* __restrict__ g,
                  const float* __restrict__ beta,
                  float* __restrict__ hout,
                  float* __restrict__ agg) {
    extern __shared__ uint32_t smemu[];
    uint32_t* sHi = smemu;                        // 128 * A_STRIDE
    uint32_t* sLo = smemu + 128 * A_STRIDE;       // 128 * A_STRIDE
    float* sO = (float*)smemu;                    // reused after MMA: 128 * O_STRIDE
    int* sClu = (int*)(smemu + 9216);

    const int b = blockIdx.y;
    const int row0 = blockIdx.x * 128;
    const int tid = threadIdx.x;

    {   // stage input tile as bf16 hi/lo (k-pairs packed in u32)
        const float4* src = (const float4*)(hin + ((size_t)b * N_SZ + row0) * H_SZ);
#pragma unroll
        for (int i = 0; i < 8; i++) {
            int idx = tid + 256 * i;              // 0..2047 float4s
            int r = idx >> 4, c4 = idx & 15;
            float4 v = src[idx];
            float hx = __bfloat162float(__float2bfloat16_rn(v.x));
            float hy = __bfloat162float(__float2bfloat16_rn(v.y));
            float hz = __bfloat162float(__float2bfloat16_rn(v.z));
            float hw = __bfloat162float(__float2bfloat16_rn(v.w));
            uint32_t base = r * A_STRIDE + c4 * 2;
            *(uint2*)&sHi[base] = make_uint2(pack_bf16(hx, hy), pack_bf16(hz, hw));
            *(uint2*)&sLo[base] = make_uint2(pack_bf16(v.x - hx, v.y - hy),
                                             pack_bf16(v.z - hz, v.w - hw));
        }
    }
    if (tid < 128) sClu[tid] = cluster[(size_t)b * N_SZ + row0 + tid];
    __syncthreads();

    const int warp = tid >> 5, lane = tid & 31;
    const int gy = lane >> 2, gx = lane & 3;
    const int rbase = warp * 16;
    const uint4* wfu = (const uint4*)wf;          // (bhi0,bhi1,blo0,blo1) per (kt,nt,lane)

    float acc[8][4];
#pragma unroll
    for (int i = 0; i < 8; i++)
#pragma unroll
        for (int j = 0; j < 4; j++) acc[i][j] = 0.f;

#pragma unroll
    for (int kt = 0; kt < 4; kt++) {
        const uint32_t* rH0 = sHi + (rbase + gy) * A_STRIDE + kt * 8;
        const uint32_t* rH1 = sHi + (rbase + gy + 8) * A_STRIDE + kt * 8;
        const uint32_t* rL0 = sLo + (rbase + gy) * A_STRIDE + kt * 8;
        const uint32_t* rL1 = sLo + (rbase + gy + 8) * A_STRIDE + kt * 8;
        uint32_t ah0 = rH0[gx], ah1 = rH1[gx], ah2 = rH0[gx + 4], ah3 = rH1[gx + 4];
        uint32_t al0 = rL0[gx], al1 = rL1[gx], al2 = rL0[gx + 4], al3 = rL1[gx + 4];
#pragma unroll
        for (int nt = 0; nt < 8; nt++) {
            uint4 bf = __ldg(&wfu[(kt * 8 + nt) * 32 + lane]);
            mma_bf16(acc[nt], ah0, ah1, ah2, ah3, bf.x, bf.y);   // hi*hi
            mma_bf16(acc[nt], al0, al1, al2, al3, bf.x, bf.y);   // lo*hi
            mma_bf16(acc[nt], ah0, ah1, ah2, ah3, bf.z, bf.w);   // hi*lo
        }
    }
    __syncthreads();   // all staging reads done; region becomes sO

    // ---- phase 1: gather aggW, LN via quad-shuffles, relu; write o into sO -------------
    const int r0 = rbase + gy, r1 = rbase + gy + 8;
    const int sa = sClu[r0], sb = sClu[r1];
    const float* aggWb = aggW + (size_t)b * 4096;
    const float* gA = aggWb + sa * 64 + gx * 2;
    const float* gB = aggWb + sb * 64 + gx * 2;

    float s1a = 0.f, s2a = 0.f, s1b = 0.f, s2b = 0.f;
#pragma unroll
    for (int nt = 0; nt < 8; nt++) {
        float2 ga = *(const float2*)(gA + nt * 8);
        float2 gb = *(const float2*)(gB + nt * 8);
        acc[nt][0] += ga.x; acc[nt][1] += ga.y;
        acc[nt][2] += gb.x; acc[nt][3] += gb.y;
        s1a += acc[nt][0] + acc[nt][1];
        s2a = fmaf(acc[nt][0], acc[nt][0], fmaf(acc[nt][1], acc[nt][1], s2a));
        s1b += acc[nt][2] + acc[nt][3];
        s2b = fmaf(acc[nt][2], acc[nt][2], fmaf(acc[nt][3], acc[nt][3], s2b));
    }
    s1a += __shfl_xor_sync(0xffffffffu, s1a, 1);
    s1a += __shfl_xor_sync(0xffffffffu, s1a, 2);
    s2a += __shfl_xor_sync(0xffffffffu, s2a, 1);
    s2a += __shfl_xor_sync(0xffffffffu, s2a, 2);
    s1b += __shfl_xor_sync(0xffffffffu, s1b, 1);
    s1b += __shfl_xor_sync(0xffffffffu, s1b, 2);
    s2b += __shfl_xor_sync(0xffffffffu, s2b, 1);
    s2b += __shfl_xor_sync(0xffffffffu, s2b, 2);

    float mua = s1a * 0.015625f;
    float rsa = rsqrtf(fmaf(-mua, mua, s2a * 0.015625f) + 1e-5f);
    float mub = s1b * 0.015625f;
    float rsb = rsqrtf(fmaf(-mub, mub, s2b * 0.015625f) + 1e-5f);

#pragma unroll
    for (int nt = 0; nt < 8; nt++) {
        const int c = nt * 8 + gx * 2;
        float2 gv = *(const float2*)(g + c);
        float2 bv = *(const float2*)(beta + c);
        float oa0 = fmaxf(0.f, fmaf((acc[nt][0] - mua) * rsa, gv.x, bv.x));
        float oa1 = fmaxf(0.f, fmaf((acc[nt][1] - mua) * rsa, gv.y, bv.y));
        float ob0 = fmaxf(0.f, fmaf((acc[nt][2] - mub) * rsb, gv.x, bv.x));
        float ob1 = fmaxf(0.f, fmaf((acc[nt][3] - mub) * rsb, gv.y, bv.y));
        *(float2*)&sO[r0 * O_STRIDE + c] = make_float2(oa0, oa1);
        *(float2*)&sO[r1 * O_STRIDE + c] = make_float2(ob0, ob1);
    }
    __syncwarp();

    // ---- phase 2: per-row coalesced hout store + coalesced segment atomics -------------
    int* gaggI = (int*)(agg + (size_t)b * 4096);
#pragma unroll
    for (int rr = 0; rr < 16; rr++) {
        const int r = rbase + rr;
        const int s = sClu[r];
        float o0 = sO[r * O_STRIDE + lane];
        float o1 = sO[r * O_STRIDE + lane + 32];
        if (WRITE_H) {
            size_t base = ((size_t)b * N_SZ + row0 + r) * H_SZ;
            hout[base + lane] = o0;
            hout[base + lane + 32] = o1;
        }
        if (o0 > 0.f) atomicMax(&gaggI[s * 64 + lane], __float_as_int(o0));
        if (o1 > 0.f) atomicMax(&gaggI[s * 64 + lane + 32], __float_as_int(o1));
    }
}

// ---------------- final: out[b,s,c] = out[b,s,c+64] = agg2[b,s,c]/max(||.||_segs, 1e-12) ----
__global__ __launch_bounds__(256)
void final_kernel(const float* __restrict__ agg2, float* __restrict__ out) {
    __shared__ float sA[64 * 64];
    __shared__ float sInv[64];
    const int b = blockIdx.x, tid = threadIdx.x;
    for (int i = tid; i < 4096; i += 256) sA[i] = agg2[(size_t)b * 4096 + i];
    __syncthreads();
    if (tid < 64) {
        float nsum = 0.f;
#pragma unroll 8
        for (int s = 0; s < 64; s++) {
            float v = sA[s * 64 + tid];
            nsum = fmaf(v, v, nsum);
        }
        float nrm = sqrtf(nsum);
        sInv[tid] = 1.f / fmaxf(nrm, 1e-12f);
    }
    __syncthreads();
    for (int i = tid; i < 8192; i += 256) {
        int s = i >> 7, ch = i & 127, c = ch & 63;
        out[(size_t)b * 8192 + i] = sA[s * 64 + c] * sInv[c];
    }
}

// ---------------- launch ----------------
extern "C" void kernel_launch(void* const* d_in, const int* in_sizes, int n_in,
                              void* d_out, int out_size) {
    const float* x = (const float*)d_in[0];
    const int* cluster = (const int*)d_in[1];
    const float* W0 = (const float*)d_in[2];
    const float* b0 = (const float*)d_in[3];
    const float* g0 = (const float*)d_in[4];
    const float* be0 = (const float*)d_in[5];
    const float* W1 = (const float*)d_in[6];
    const float* b1 = (const float*)d_in[7];
    const float* g1 = (const float*)d_in[8];
    const float* be1 = (const float*)d_in[9];
    const float* W2 = (const float*)d_in[10];
    const float* b2 = (const float*)d_in[11];
    const float* g2 = (const float*)d_in[12];
    const float* be2 = (const float*)d_in[13];
    float* out = (float*)d_out;

    float *hA, *hB, *agg, *aggW, *wfrag;
    cudaGetSymbolAddress((void**)&hA, g_hA);
    cudaGetSymbolAddress((void**)&hB, g_hB);
    cudaGetSymbolAddress((void**)&agg, g_agg);
    cudaGetSymbolAddress((void**)&aggW, g_aggW);
    cudaGetSymbolAddress((void**)&wfrag, g_wfrag);
    float* agg0 = agg;
    float* agg1 = agg + (size_t)B_SZ * 4096;
    float* agg2 = agg + (size_t)2 * B_SZ * 4096;

    cudaFuncSetAttribute(layer_kernel<true>, cudaFuncAttributeMaxDynamicSharedMemorySize, SMEM_LAYER);
    cudaFuncSetAttribute(layer_kernel<false>, cudaFuncAttributeMaxDynamicSharedMemorySize, SMEM_LAYER);

    prep_kernel<<<1538, 256>>>(agg, W1, W2, wfrag);

    dim3 grid(N_SZ / 128, B_SZ);
    dim3 agrid(4, B_SZ);
    layer0_kernel<<<grid, 256>>>(x, cluster, W0, b0, g0, be0, hA, agg0);
    aggw_kernel<<<agrid, 256>>>(agg0, W1 + 64 * 64, b1, aggW);
    layer_kernel<true><<<grid, 256, SMEM_LAYER>>>(hA, aggW, cluster, wfrag, g1, be1, hB, agg1);
    aggw_kernel<<<agrid, 256>>>(agg1, W2 + 64 * 64, b2, aggW);
    layer_kernel<false><<<grid, 256, SMEM_LAYER>>>(hB, aggW, cluster, wfrag + 4096, g2, be2, nullptr, agg2);
    final_kernel<<<B_SZ, 256>>>(agg2, out);
}